// round 6
// baseline (speedup 1.0000x reference)
#include <cuda_runtime.h>
#include <cuda_pipeline.h>
#include <cstddef>

// LocalVariation: out[b,k,y,x] = x[b,y,x] - x[b, clamp(y+i-2), clamp(x+j-2)]
// k enumerates 24 off-center (i,j) in a 5x5 window. x: [16,1,512,512] f32.
//
// R5: persistent CTAs (grid = 148*3, forced resident via launch_bounds) with
// DOUBLE-BUFFERED smem staging over cp.async: while a tile's 24 streaming
// stores drain, the next tile's 8 input rows stream into the other buffer.
// Removes the stage->sync->store serialization that capped DRAM duty cycle.

#define KSZ 5
#define P   2
#define NBR 24
#define H   512
#define W   512
#define BATCH 16
#define ROWS_PER_CTA 4
#define SROWS (ROWS_PER_CTA + KSZ - 1)     // 8 staged rows per tile
#define SROW 520                            // padded row stride (16B-aligned)
#define SCOLS 516                           // valid cols: x in [-2, 513]
#define TILES_PER_B (H / ROWS_PER_CTA)      // 128
#define NTILES (BATCH * TILES_PER_B)        // 2048
#define NSM 148
#define CTAS_PER_SM 3
#define PGRID (NSM * CTAS_PER_SM)           // 444 persistent CTAs

__device__ __forceinline__ void stage_tile(const float* __restrict__ x,
                                           int tile, float* __restrict__ dst,
                                           int tid)
{
    const int b  = tile >> 7;                       // tile / 128
    const int y0 = (tile & 127) * ROWS_PER_CTA;
    const float* __restrict__ xb = x + (size_t)b * (H * W);
    #pragma unroll 2
    for (int idx = tid; idx < SROWS * SCOLS; idx += 512) {
        const int r   = idx / SCOLS;
        const int col = idx - r * SCOLS;            // maps to x = col-2
        int gy = y0 + r - P;
        gy = gy < 0 ? 0 : (gy > H - 1 ? H - 1 : gy);
        int gx = col - P;
        gx = gx < 0 ? 0 : (gx > W - 1 ? W - 1 : gx);
        // fire-and-forget gmem->smem; never blocks the warp on data return
        __pipeline_memcpy_async(&dst[r * SROW + col], &xb[gy * W + gx], 4);
    }
    __pipeline_commit();
}

__global__ __launch_bounds__(512, CTAS_PER_SM)
void LocalVariation_kernel(const float* __restrict__ x, float* __restrict__ out)
{
    __shared__ float s[2][SROWS * SROW];            // 2 x 16.6 KB

    const int tid = threadIdx.x;                    // 0..511
    const int r0  = tid >> 7;                       // output row within tile
    const int x0  = (tid & 127) * 4;                // 4 pixels per thread

    int t = blockIdx.x;                             // < PGRID <= NTILES
    stage_tile(x, t, s[0], tid);

    int buf = 0;
    for (; t < NTILES; t += PGRID) {
        __pipeline_wait_prior(0);                   // current buffer's copies done
        __syncthreads();                            // visible to all; prev reads done

        const int tn = t + PGRID;
        if (tn < NTILES) stage_tile(x, tn, s[buf ^ 1], tid);  // overlaps stores below

        const int b  = t >> 7;
        const int y0 = (t & 127) * ROWS_PER_CTA;

        const float* sp = &s[buf][r0 * SROW + x0];
        const float c0 = sp[2 * SROW + 2];
        const float c1 = sp[2 * SROW + 3];
        const float c2 = sp[2 * SROW + 4];
        const float c3 = sp[2 * SROW + 5];

        float* __restrict__ ob =
            out + (((size_t)b * NBR) * H + (y0 + r0)) * W + x0;

        int k = 0;
        #pragma unroll
        for (int i = 0; i < KSZ; i++) {
            const float4 lo = *reinterpret_cast<const float4*>(sp);
            const float4 hi = *reinterpret_cast<const float4*>(sp + 4);
            const float w0 = lo.x, w1 = lo.y, w2 = lo.z, w3 = lo.w;
            const float w4 = hi.x, w5 = hi.y, w6 = hi.z, w7 = hi.w;
            sp += SROW;

            #pragma unroll
            for (int j = 0; j < KSZ; j++) {
                if (i == P && j == P) continue;
                const float n0 = (j == 0) ? w0 : (j == 1) ? w1 : (j == 2) ? w2 : (j == 3) ? w3 : w4;
                const float n1 = (j == 0) ? w1 : (j == 1) ? w2 : (j == 2) ? w3 : (j == 3) ? w4 : w5;
                const float n2 = (j == 0) ? w2 : (j == 1) ? w3 : (j == 2) ? w4 : (j == 3) ? w5 : w6;
                const float n3 = (j == 0) ? w3 : (j == 1) ? w4 : (j == 2) ? w5 : (j == 3) ? w6 : w7;
                float4 v;
                v.x = c0 - n0;
                v.y = c1 - n1;
                v.z = c2 - n2;
                v.w = c3 - n3;
                __stcs(reinterpret_cast<float4*>(ob + (size_t)k * (H * W)), v);
                k++;
            }
        }

        buf ^= 1;
    }
}

extern "C" void kernel_launch(void* const* d_in, const int* in_sizes, int n_in,
                              void* d_out, int out_size)
{
    (void)in_sizes; (void)n_in; (void)out_size;
    const float* x = (const float*)d_in[0];
    float* out = (float*)d_out;
    LocalVariation_kernel<<<PGRID, 512>>>(x, out);
}

// round 7
// speedup vs baseline: 1.1536x; 1.1536x over previous
#include <cuda_runtime.h>
#include <cstddef>

// LocalVariation: out[b,k,y,x] = x[b,y,x] - x[b, clamp(y+i-2), clamp(x+j-2)]
// k enumerates 24 off-center (i,j) in a 5x5 window. x: [16,1,512,512] f32.
//
// R6: SMEM-FREE. Each thread gathers its 5-row x 8-wide window directly with
// vectorized LDG.128 (input is L1/L2 resident; adjacent threads' windows
// overlap -> warp-coalesced, L1 hits). No STS, no LDS, no __syncthreads:
// stores start one L2 round-trip after CTA start and row i+1 loads overlap
// row i stores. Store stream unchanged: 24 streaming STG.128 per thread.

#define KSZ 5
#define P   2
#define NBR 24
#define H   512
#define W   512
#define BATCH 16
#define ROWS_PER_CTA 4

__global__ __launch_bounds__(512, 3)
void LocalVariation_kernel(const float* __restrict__ x, float* __restrict__ out)
{
    const int tid = threadIdx.x;                  // 0..511
    const int r0  = tid >> 7;                     // row within tile (0..3)
    const int x0  = (tid & 127) * 4;              // 4 pixels per thread
    const int y   = blockIdx.x * ROWS_PER_CTA + r0;
    const int b   = blockIdx.y;

    const float* __restrict__ xb = x + (size_t)b * (H * W);

    // Center 4 pixels: aligned LDG.128 at (y, x0).
    const float4 cv = __ldg(reinterpret_cast<const float4*>(xb + y * W + x0));
    const float c0 = cv.x, c1 = cv.y, c2 = cv.z, c3 = cv.w;

    float* __restrict__ ob =
        out + (((size_t)b * NBR) * H + y) * W + x0;

    const bool has_lo = (x0 > 0);        // left  window part in-row?
    const bool has_hi = (x0 < W - 4);    // right window part in-row?

    int k = 0;
    #pragma unroll
    for (int i = 0; i < KSZ; i++) {
        int gy = y + i - P;
        gy = gy < 0 ? 0 : (gy > H - 1 ? H - 1 : gy);
        const float* __restrict__ rp = xb + gy * W;

        // Window w[m] = row value at x = clamp(x0 - 2 + m), m = 0..7.
        const float4 v1 = __ldg(reinterpret_cast<const float4*>(rp + x0));
        float w0, w1, w6, w7;
        if (has_lo) {
            const float4 v0 = __ldg(reinterpret_cast<const float4*>(rp + x0 - 4));
            w0 = v0.z; w1 = v0.w;                 // x0-2, x0-1
        } else {
            w0 = v1.x; w1 = v1.x;                 // replicate pad: clamp to x=0
        }
        if (has_hi) {
            const float4 v2 = __ldg(reinterpret_cast<const float4*>(rp + x0 + 4));
            w6 = v2.x; w7 = v2.y;                 // x0+4, x0+5
        } else {
            w6 = v1.w; w7 = v1.w;                 // clamp to x=511
        }
        const float w2 = v1.x, w3 = v1.y, w4 = v1.z, w5 = v1.w;

        #pragma unroll
        for (int j = 0; j < KSZ; j++) {
            if (i == P && j == P) continue;
            // neighbor for output pixel dx is w[dx + j]
            const float n0 = (j == 0) ? w0 : (j == 1) ? w1 : (j == 2) ? w2 : (j == 3) ? w3 : w4;
            const float n1 = (j == 0) ? w1 : (j == 1) ? w2 : (j == 2) ? w3 : (j == 3) ? w4 : w5;
            const float n2 = (j == 0) ? w2 : (j == 1) ? w3 : (j == 2) ? w4 : (j == 3) ? w5 : w6;
            const float n3 = (j == 0) ? w3 : (j == 1) ? w4 : (j == 2) ? w5 : (j == 3) ? w6 : w7;
            float4 v;
            v.x = c0 - n0;
            v.y = c1 - n1;
            v.z = c2 - n2;
            v.w = c3 - n3;
            __stcs(reinterpret_cast<float4*>(ob + (size_t)k * (H * W)), v);
            k++;
        }
    }
}

extern "C" void kernel_launch(void* const* d_in, const int* in_sizes, int n_in,
                              void* d_out, int out_size)
{
    (void)in_sizes; (void)n_in; (void)out_size;
    const float* x = (const float*)d_in[0];
    float* out = (float*)d_out;
    dim3 grid(H / ROWS_PER_CTA, BATCH);
    LocalVariation_kernel<<<grid, 512>>>(x, out);
}

// round 11
// speedup vs baseline: 1.1722x; 1.0161x over previous
#include <cuda_runtime.h>
#include <cstddef>

// LocalVariation: out[b,k,y,x] = x[b,y,x] - x[b, clamp(y+i-2), clamp(x+j-2)]
// k enumerates 24 off-center (i,j) in a 5x5 window. x: [16,1,512,512] f32.
//
// R7: same SMEM-free register-gather structure as R6, but FINER CTA
// granularity: 2 rows / 256 threads per CTA -> 4096 CTAs. Per-CTA duration
// halves (~6.5us), so the final-wave drain / straggler tail costs half as
// much and work-stealing balances better. Store stream unchanged:
// 24 streaming STG.128 per thread.

#define KSZ 5
#define P   2
#define NBR 24
#define H   512
#define W   512
#define BATCH 16
#define ROWS_PER_CTA 2
#define CTA_THREADS 256

__global__ __launch_bounds__(CTA_THREADS, 6)
void LocalVariation_kernel(const float* __restrict__ x, float* __restrict__ out)
{
    const int tid = threadIdx.x;                  // 0..255
    const int r0  = tid >> 7;                     // row within tile (0..1)
    const int x0  = (tid & 127) * 4;              // 4 pixels per thread
    const int y   = blockIdx.x * ROWS_PER_CTA + r0;
    const int b   = blockIdx.y;

    const float* __restrict__ xb = x + (size_t)b * (H * W);

    // Center 4 pixels: aligned LDG.128 at (y, x0).
    const float4 cv = __ldg(reinterpret_cast<const float4*>(xb + y * W + x0));
    const float c0 = cv.x, c1 = cv.y, c2 = cv.z, c3 = cv.w;

    float* __restrict__ ob =
        out + (((size_t)b * NBR) * H + y) * W + x0;

    const bool has_lo = (x0 > 0);        // left  window part in-row?
    const bool has_hi = (x0 < W - 4);    // right window part in-row?

    int k = 0;
    #pragma unroll
    for (int i = 0; i < KSZ; i++) {
        int gy = y + i - P;
        gy = gy < 0 ? 0 : (gy > H - 1 ? H - 1 : gy);
        const float* __restrict__ rp = xb + gy * W;

        // Window w[m] = row value at x = clamp(x0 - 2 + m), m = 0..7.
        const float4 v1 = __ldg(reinterpret_cast<const float4*>(rp + x0));
        float w0, w1, w6, w7;
        if (has_lo) {
            const float4 v0 = __ldg(reinterpret_cast<const float4*>(rp + x0 - 4));
            w0 = v0.z; w1 = v0.w;                 // x0-2, x0-1
        } else {
            w0 = v1.x; w1 = v1.x;                 // replicate pad: clamp to x=0
        }
        if (has_hi) {
            const float4 v2 = __ldg(reinterpret_cast<const float4*>(rp + x0 + 4));
            w6 = v2.x; w7 = v2.y;                 // x0+4, x0+5
        } else {
            w6 = v1.w; w7 = v1.w;                 // clamp to x=511
        }
        const float w2 = v1.x, w3 = v1.y, w4 = v1.z, w5 = v1.w;

        #pragma unroll
        for (int j = 0; j < KSZ; j++) {
            if (i == P && j == P) continue;
            // neighbor for output pixel dx is w[dx + j]
            const float n0 = (j == 0) ? w0 : (j == 1) ? w1 : (j == 2) ? w2 : (j == 3) ? w3 : w4;
            const float n1 = (j == 0) ? w1 : (j == 1) ? w2 : (j == 2) ? w3 : (j == 3) ? w4 : w5;
            const float n2 = (j == 0) ? w2 : (j == 1) ? w3 : (j == 2) ? w4 : (j == 3) ? w5 : w6;
            const float n3 = (j == 0) ? w3 : (j == 1) ? w4 : (j == 2) ? w5 : (j == 3) ? w6 : w7;
            float4 v;
            v.x = c0 - n0;
            v.y = c1 - n1;
            v.z = c2 - n2;
            v.w = c3 - n3;
            __stcs(reinterpret_cast<float4*>(ob + (size_t)k * (H * W)), v);
            k++;
        }
    }
}

extern "C" void kernel_launch(void* const* d_in, const int* in_sizes, int n_in,
                              void* d_out, int out_size)
{
    (void)in_sizes; (void)n_in; (void)out_size;
    const float* x = (const float*)d_in[0];
    float* out = (float*)d_out;
    dim3 grid(H / ROWS_PER_CTA, BATCH);
    LocalVariation_kernel<<<grid, CTA_THREADS>>>(x, out);
}